// round 2
// baseline (speedup 1.0000x reference)
#include <cuda_runtime.h>

#define N_NODES 100000
#define N_EDGES 3200000
#define DFEAT   256
#define UNITS   256

// ---------------- device scratch (no runtime allocation allowed) ----------------
__device__ float d_h[(size_t)N_NODES * UNITS];   // h = X @ W
__device__ int   d_counts[N_NODES];
__device__ int   d_offsets[N_NODES + 1];
__device__ int   d_cursor[N_NODES];
__device__ int   d_csr_col[N_EDGES];
__device__ float d_csr_val[N_EDGES];

// ---------------- kernel 1: zero the row histogram ----------------
__global__ void zero_counts_kernel() {
    int i = blockIdx.x * blockDim.x + threadIdx.x;
    if (i < N_NODES) d_counts[i] = 0;
}

// ---------------- kernel 2: histogram of edge rows ----------------
__global__ void hist_kernel(const int* __restrict__ erow) {
    int e = blockIdx.x * blockDim.x + threadIdx.x;
    if (e < N_EDGES) atomicAdd(&d_counts[erow[e]], 1);
}

// ---------------- kernel 3: single-block exclusive scan -> offsets & cursor ----------------
__global__ void scan_kernel() {
    __shared__ int s[1024];
    __shared__ int carry_s;
    int tid = threadIdx.x;
    if (tid == 0) carry_s = 0;
    __syncthreads();
    for (int base = 0; base < N_NODES; base += 1024) {
        int i = base + tid;
        int v = (i < N_NODES) ? d_counts[i] : 0;
        s[tid] = v;
        __syncthreads();
        // Hillis-Steele inclusive scan
        #pragma unroll
        for (int off = 1; off < 1024; off <<= 1) {
            int t = (tid >= off) ? s[tid - off] : 0;
            __syncthreads();
            s[tid] += t;
            __syncthreads();
        }
        int incl = s[tid];
        int excl = incl - v;
        int carry = carry_s;
        if (i < N_NODES) {
            d_offsets[i] = carry + excl;
            d_cursor[i]  = carry + excl;
        }
        __syncthreads();
        if (tid == 1023) carry_s = carry + incl;
        __syncthreads();
    }
    if (tid == 0) d_offsets[N_NODES] = carry_s;
}

// ---------------- kernel 4: scatter edges into CSR order ----------------
__global__ void scatter_kernel(const int* __restrict__ erow,
                               const int* __restrict__ ecol,
                               const float* __restrict__ eval) {
    int e = blockIdx.x * blockDim.x + threadIdx.x;
    if (e < N_EDGES) {
        int r = erow[e];
        int p = atomicAdd(&d_cursor[r], 1);
        d_csr_col[p] = ecol[e];
        d_csr_val[p] = eval[e];
    }
}

// ---------------- kernel 5: SIMT fp32 GEMM, 64x64 tile, 4x4 per thread ----------------
__global__ void gemm_kernel(const float* __restrict__ X, const float* __restrict__ W) {
    __shared__ float As[64][16];
    __shared__ float Bs[16][64];
    int tid = threadIdx.x;                // 0..255
    int ty = tid >> 4;                    // 0..15
    int tx = tid & 15;                    // 0..15
    int rowBase = blockIdx.y * 64;
    int colBase = blockIdx.x * 64;

    int aRow = tid >> 2;                  // 0..63
    int aCol = (tid & 3) * 4;             // 0,4,8,12
    int bRow = tid >> 4;                  // 0..15
    int bCol = (tid & 15) * 4;            // 0..60

    float acc[4][4] = {};

    for (int k0 = 0; k0 < DFEAT; k0 += 16) {
        int gr = rowBase + aRow;
        float4 av = (gr < N_NODES)
            ? *(const float4*)&X[(size_t)gr * DFEAT + k0 + aCol]
            : make_float4(0.f, 0.f, 0.f, 0.f);
        As[aRow][aCol + 0] = av.x;
        As[aRow][aCol + 1] = av.y;
        As[aRow][aCol + 2] = av.z;
        As[aRow][aCol + 3] = av.w;

        float4 bv = *(const float4*)&W[(size_t)(k0 + bRow) * UNITS + colBase + bCol];
        Bs[bRow][bCol + 0] = bv.x;
        Bs[bRow][bCol + 1] = bv.y;
        Bs[bRow][bCol + 2] = bv.z;
        Bs[bRow][bCol + 3] = bv.w;
        __syncthreads();

        #pragma unroll
        for (int kk = 0; kk < 16; kk++) {
            float a[4], b[4];
            #pragma unroll
            for (int i = 0; i < 4; i++) a[i] = As[ty * 4 + i][kk];
            float4 b4 = *(const float4*)&Bs[kk][tx * 4];
            b[0] = b4.x; b[1] = b4.y; b[2] = b4.z; b[3] = b4.w;
            #pragma unroll
            for (int i = 0; i < 4; i++)
                #pragma unroll
                for (int j = 0; j < 4; j++)
                    acc[i][j] += a[i] * b[j];
        }
        __syncthreads();
    }

    #pragma unroll
    for (int i = 0; i < 4; i++) {
        int gr = rowBase + ty * 4 + i;
        if (gr < N_NODES) {
            float4 v = make_float4(acc[i][0], acc[i][1], acc[i][2], acc[i][3]);
            *(float4*)&d_h[(size_t)gr * UNITS + colBase + tx * 4] = v;
        }
    }
}

// ---------------- kernel 6: pull-SpMM + bias + ReLU (one CTA per row) ----------------
__global__ void spmm_kernel(const float* __restrict__ b, float* __restrict__ out) {
    int row = blockIdx.x;
    int t = threadIdx.x;                   // column 0..255
    int start = d_offsets[row];
    int end   = d_offsets[row + 1];
    float acc = 0.f;
    for (int e = start; e < end; e++) {
        int   c = d_csr_col[e];
        float v = d_csr_val[e];
        acc += v * d_h[(size_t)c * UNITS + t];
    }
    float r = acc + b[t];
    out[(size_t)row * UNITS + t] = fmaxf(r, 0.f);
}

// ---------------- launch ----------------
extern "C" void kernel_launch(void* const* d_in, const int* in_sizes, int n_in,
                              void* d_out, int out_size) {
    const float* X    = (const float*)d_in[0];
    const int*   erow = (const int*)  d_in[1];
    const int*   ecol = (const int*)  d_in[2];
    const float* eval = (const float*)d_in[3];
    const float* W    = (const float*)d_in[4];
    const float* bias = (const float*)d_in[5];
    float* out = (float*)d_out;

    (void)in_sizes; (void)n_in; (void)out_size;

    zero_counts_kernel<<<(N_NODES + 255) / 256, 256>>>();
    hist_kernel<<<(N_EDGES + 255) / 256, 256>>>(erow);
    scan_kernel<<<1, 1024>>>();
    scatter_kernel<<<(N_EDGES + 255) / 256, 256>>>(erow, ecol, eval);
    gemm_kernel<<<dim3(UNITS / 64, (N_NODES + 63) / 64), 256>>>(X, W);
    spmm_kernel<<<N_NODES, 256>>>(bias, out);
}

// round 4
// speedup vs baseline: 2.7147x; 2.7147x over previous
#include <cuda_runtime.h>
#include <cstdint>

#define N_NODES 100000
#define N_EDGES 3200000
#define DFEAT   256
#define UNITS   256

// GEMM tiling (mma.sync tf32)
#define GEMM_BM 128
#define GEMM_BN 128
#define GEMM_BK 32
#define KTILES  (DFEAT / GEMM_BK)    // 8
#define A_STRIDE 36                  // 128x32 tile, padded (conflict-free frag loads)
#define B_STRIDE 132                 // 32x128 tile, padded
#define SMEM_A_ELEMS (GEMM_BM * A_STRIDE)     // 4608
#define SMEM_B_ELEMS (GEMM_BK * B_STRIDE)     // 4224
#define SMEM_TOTAL_F (2 * SMEM_A_ELEMS + 2 * SMEM_B_ELEMS)   // 17664 floats
#define SMEM_TOTAL_B (SMEM_TOTAL_F * 4)                      // 70656 bytes

// ---------------- device scratch ----------------
__device__ float d_h[(size_t)N_NODES * UNITS];    // h = X @ W
__device__ int   d_counts[N_NODES];
__device__ int   d_offsets[N_NODES + 1];
__device__ int   d_cursor[N_NODES];
__device__ int   d_blocksums[512];
__device__ int   d_csr_col[N_EDGES];
__device__ float d_csr_val[N_EDGES];

// ---------------- helpers ----------------
__device__ __forceinline__ float tf32r(float x) {   // round-to-nearest tf32
    uint32_t r;
    asm("cvt.rna.tf32.f32 %0, %1;" : "=r"(r) : "f"(x));
    return __uint_as_float(r);
}
__device__ __forceinline__ void mma_tf32(float* c, const uint32_t* a, const uint32_t* b) {
    asm volatile(
        "mma.sync.aligned.m16n8k8.row.col.f32.tf32.tf32.f32 "
        "{%0,%1,%2,%3}, {%4,%5,%6,%7}, {%8,%9}, {%0,%1,%2,%3};"
        : "+f"(c[0]), "+f"(c[1]), "+f"(c[2]), "+f"(c[3])
        : "r"(a[0]), "r"(a[1]), "r"(a[2]), "r"(a[3]), "r"(b[0]), "r"(b[1]));
}

// ---------------- CSR build ----------------
__global__ void zero_counts_kernel() {
    int i = blockIdx.x * blockDim.x + threadIdx.x;
    if (i < N_NODES) d_counts[i] = 0;
}
__global__ void hist_kernel(const int* __restrict__ erow) {
    int e = blockIdx.x * blockDim.x + threadIdx.x;
    if (e < N_EDGES) atomicAdd(&d_counts[erow[e]], 1);
}
__global__ void scan1_kernel() {
    __shared__ int s[256];
    int t = threadIdx.x;
    int i = blockIdx.x * 256 + t;
    int v = (i < N_NODES) ? d_counts[i] : 0;
    s[t] = v;
    __syncthreads();
    #pragma unroll
    for (int off = 1; off < 256; off <<= 1) {
        int x = (t >= off) ? s[t - off] : 0;
        __syncthreads();
        s[t] += x;
        __syncthreads();
    }
    if (i < N_NODES) d_offsets[i] = s[t] - v;   // temp: block-local exclusive
    if (t == 255) d_blocksums[blockIdx.x] = s[255];
}
__global__ void scan2_kernel(int nblocks) {
    __shared__ int s[512];
    int t = threadIdx.x;
    int v = (t < nblocks) ? d_blocksums[t] : 0;
    s[t] = v;
    __syncthreads();
    #pragma unroll
    for (int off = 1; off < 512; off <<= 1) {
        int x = (t >= off) ? s[t - off] : 0;
        __syncthreads();
        s[t] += x;
        __syncthreads();
    }
    if (t < nblocks) d_blocksums[t] = s[t] - v;   // exclusive base
    if (t == 511) d_offsets[N_NODES] = s[511];
}
__global__ void scan3_kernel() {
    int i = blockIdx.x * 256 + threadIdx.x;
    if (i < N_NODES) {
        int o = d_blocksums[blockIdx.x] + d_offsets[i];
        d_offsets[i] = o;
        d_cursor[i]  = o;
    }
}
__global__ void scatter_kernel(const int* __restrict__ erow,
                               const int* __restrict__ ecol,
                               const float* __restrict__ eval) {
    int e = blockIdx.x * blockDim.x + threadIdx.x;
    if (e < N_EDGES) {
        int r = erow[e];
        int p = atomicAdd(&d_cursor[r], 1);
        d_csr_col[p] = ecol[e];
        d_csr_val[p] = eval[e];
    }
}

// ---------------- GEMM: h = X @ W via mma.sync tf32, 3xTF32 compensated ----------------
// CTA: 128x128 tile, 256 threads = 8 warps (4 x 2), warp tile 32x64.
__global__ __launch_bounds__(256, 2) void gemm_mma_kernel(const float* __restrict__ X,
                                                          const float* __restrict__ W) {
    extern __shared__ float smem[];
    float* As_h = smem;                                   // [128][36]
    float* As_l = smem + SMEM_A_ELEMS;
    float* Bs_h = smem + 2 * SMEM_A_ELEMS;                // [32][132]
    float* Bs_l = smem + 2 * SMEM_A_ELEMS + SMEM_B_ELEMS;

    int tid = threadIdx.x;
    int wid = tid >> 5;
    int lane = tid & 31;
    int warp_m = wid & 3;          // 0..3
    int warp_n = wid >> 2;         // 0..1
    int rowBase = blockIdx.x * GEMM_BM;
    int colBase = blockIdx.y * GEMM_BN;
    int lr = lane >> 2;            // 0..7
    int lc = lane & 3;             // 0..3

    float acc[2][8][4];
    #pragma unroll
    for (int im = 0; im < 2; im++)
        #pragma unroll
        for (int in = 0; in < 8; in++)
            #pragma unroll
            for (int q = 0; q < 4; q++) acc[im][in][q] = 0.f;

    for (int kt = 0; kt < KTILES; kt++) {
        int k0 = kt * GEMM_BK;
        // A tile: 128 rows x 32 cols, 1024 float4, 4 per thread
        #pragma unroll
        for (int j = 0; j < 4; j++) {
            int f = tid + j * 256;
            int row = f >> 3, q = f & 7;
            int gr = rowBase + row;
            float4 v = make_float4(0.f, 0.f, 0.f, 0.f);
            if (gr < N_NODES) v = *(const float4*)&X[(size_t)gr * DFEAT + k0 + q * 4];
            float4 h4, l4;
            h4.x = tf32r(v.x); l4.x = tf32r(v.x - h4.x);
            h4.y = tf32r(v.y); l4.y = tf32r(v.y - h4.y);
            h4.z = tf32r(v.z); l4.z = tf32r(v.z - h4.z);
            h4.w = tf32r(v.w); l4.w = tf32r(v.w - h4.w);
            *(float4*)&As_h[row * A_STRIDE + q * 4] = h4;
            *(float4*)&As_l[row * A_STRIDE + q * 4] = l4;
        }
        // B tile: 32 k-rows x 128 n-cols straight from W (row-major [k][n])
        #pragma unroll
        for (int j = 0; j < 4; j++) {
            int f = tid + j * 256;
            int kr = f >> 5, q = f & 31;
            float4 v = *(const float4*)&W[(size_t)(k0 + kr) * UNITS + colBase + q * 4];
            float4 h4, l4;
            h4.x = tf32r(v.x); l4.x = tf32r(v.x - h4.x);
            h4.y = tf32r(v.y); l4.y = tf32r(v.y - h4.y);
            h4.z = tf32r(v.z); l4.z = tf32r(v.z - h4.z);
            h4.w = tf32r(v.w); l4.w = tf32r(v.w - h4.w);
            *(float4*)&Bs_h[kr * B_STRIDE + q * 4] = h4;
            *(float4*)&Bs_l[kr * B_STRIDE + q * 4] = l4;
        }
        __syncthreads();

        #pragma unroll
        for (int ks = 0; ks < 4; ks++) {
            int kk = ks * 8;
            uint32_t a_h[2][4], a_l[2][4];
            #pragma unroll
            for (int im = 0; im < 2; im++) {
                int m0 = warp_m * 32 + im * 16;
                const float* ph = &As_h[(m0 + lr) * A_STRIDE + kk + lc];
                const float* pl = &As_l[(m0 + lr) * A_STRIDE + kk + lc];
                a_h[im][0] = __float_as_uint(ph[0]);
                a_h[im][1] = __float_as_uint(ph[8 * A_STRIDE]);
                a_h[im][2] = __float_as_uint(ph[4]);
                a_h[im][3] = __float_as_uint(ph[8 * A_STRIDE + 4]);
                a_l[im][0] = __float_as_uint(pl[0]);
                a_l[im][1] = __float_as_uint(pl[8 * A_STRIDE]);
                a_l[im][2] = __float_as_uint(pl[4]);
                a_l[im][3] = __float_as_uint(pl[8 * A_STRIDE + 4]);
            }
            #pragma unroll
            for (int in = 0; in < 8; in++) {
                int n = warp_n * 64 + in * 8 + lr;
                uint32_t b_h[2], b_l[2];
                b_h[0] = __float_as_uint(Bs_h[(kk + lc) * B_STRIDE + n]);
                b_h[1] = __float_as_uint(Bs_h[(kk + 4 + lc) * B_STRIDE + n]);
                b_l[0] = __float_as_uint(Bs_l[(kk + lc) * B_STRIDE + n]);
                b_l[1] = __float_as_uint(Bs_l[(kk + 4 + lc) * B_STRIDE + n]);
                #pragma unroll
                for (int im = 0; im < 2; im++) {
                    mma_tf32(acc[im][in], a_h[im], b_h);   // hi*hi
                    mma_tf32(acc[im][in], a_h[im], b_l);   // hi*lo
                    mma_tf32(acc[im][in], a_l[im], b_h);   // lo*hi
                }
            }
        }
        __syncthreads();
    }

    // Epilogue: write to d_h. c0,c1: (row, col..col+1); c2,c3: (row+8, ...)
    #pragma unroll
    for (int im = 0; im < 2; im++) {
        int m = rowBase + warp_m * 32 + im * 16 + lr;
        #pragma unroll
        for (int in = 0; in < 8; in++) {
            int col = colBase + warp_n * 64 + in * 8 + 2 * lc;
            if (m < N_NODES)
                *(float2*)&d_h[(size_t)m * UNITS + col] =
                    make_float2(acc[im][in][0], acc[im][in][1]);
            if (m + 8 < N_NODES)
                *(float2*)&d_h[(size_t)(m + 8) * UNITS + col] =
                    make_float2(acc[im][in][2], acc[im][in][3]);
        }
    }
}

// ---------------- SpMM + bias + ReLU: 4 rows/CTA, float4/thread ----------------
__global__ __launch_bounds__(256) void spmm_kernel(const float* __restrict__ b,
                                                   float* __restrict__ out) {
    int group = threadIdx.x >> 6;          // 0..3 -> row within CTA
    int lane  = threadIdx.x & 63;          // 0..63 -> column group
    int row = blockIdx.x * 4 + group;
    if (row >= N_NODES) return;
    int col4 = lane * 4;

    int e   = d_offsets[row];
    int end = d_offsets[row + 1];
    float4 acc = make_float4(0.f, 0.f, 0.f, 0.f);

    for (; e + 4 <= end; e += 4) {
        int   c0 = d_csr_col[e + 0], c1 = d_csr_col[e + 1];
        int   c2 = d_csr_col[e + 2], c3 = d_csr_col[e + 3];
        float v0 = d_csr_val[e + 0], v1 = d_csr_val[e + 1];
        float v2 = d_csr_val[e + 2], v3 = d_csr_val[e + 3];
        float4 h0 = *(const float4*)&d_h[(size_t)c0 * UNITS + col4];
        float4 h1 = *(const float4*)&d_h[(size_t)c1 * UNITS + col4];
        float4 h2 = *(const float4*)&d_h[(size_t)c2 * UNITS + col4];
        float4 h3 = *(const float4*)&d_h[(size_t)c3 * UNITS + col4];
        acc.x += v0 * h0.x + v1 * h1.x + v2 * h2.x + v3 * h3.x;
        acc.y += v0 * h0.y + v1 * h1.y + v2 * h2.y + v3 * h3.y;
        acc.z += v0 * h0.z + v1 * h1.z + v2 * h2.z + v3 * h3.z;
        acc.w += v0 * h0.w + v1 * h1.w + v2 * h2.w + v3 * h3.w;
    }
    for (; e < end; e++) {
        int   c = d_csr_col[e];
        float v = d_csr_val[e];
        float4 h = *(const float4*)&d_h[(size_t)c * UNITS + col4];
        acc.x += v * h.x; acc.y += v * h.y; acc.z += v * h.z; acc.w += v * h.w;
    }
    float4 bb = *(const float4*)&b[col4];
    float4 r;
    r.x = fmaxf(acc.x + bb.x, 0.f);
    r.y = fmaxf(acc.y + bb.y, 0.f);
    r.z = fmaxf(acc.z + bb.z, 0.f);
    r.w = fmaxf(acc.w + bb.w, 0.f);
    *(float4*)&out[(size_t)row * UNITS + col4] = r;
}

// ---------------- launch ----------------
extern "C" void kernel_launch(void* const* d_in, const int* in_sizes, int n_in,
                              void* d_out, int out_size) {
    const float* X    = (const float*)d_in[0];
    const int*   erow = (const int*)  d_in[1];
    const int*   ecol = (const int*)  d_in[2];
    const float* eval = (const float*)d_in[3];
    const float* W    = (const float*)d_in[4];
    const float* bias = (const float*)d_in[5];
    float* out = (float*)d_out;
    (void)in_sizes; (void)n_in; (void)out_size;

    const int nscan = (N_NODES + 255) / 256;   // 391

    cudaFuncSetAttribute(gemm_mma_kernel,
                         cudaFuncAttributeMaxDynamicSharedMemorySize, SMEM_TOTAL_B);

    zero_counts_kernel<<<nscan, 256>>>();
    hist_kernel<<<(N_EDGES + 255) / 256, 256>>>(erow);
    scan1_kernel<<<nscan, 256>>>();
    scan2_kernel<<<1, 512>>>(nscan);
    scan3_kernel<<<nscan, 256>>>();
    scatter_kernel<<<(N_EDGES + 255) / 256, 256>>>(erow, ecol, eval);
    gemm_mma_kernel<<<dim3((N_NODES + GEMM_BM - 1) / GEMM_BM, UNITS / GEMM_BN),
                     256, SMEM_TOTAL_B>>>(X, W);
    spmm_kernel<<<(N_NODES + 3) / 4, 256>>>(bias, out);
}